// round 13
// baseline (speedup 1.0000x reference)
#include <cuda_runtime.h>
#include <cuda_fp16.h>
#include <cstdint>

#define B_DIM 512
#define F_DIM 784
#define R_DIM 512
#define C_DIM 16
#define D_DIM 49
#define HALF_LOG_2PI 0.9189385332046727f

// Scratch (allocation-free rule: __device__ globals)
__device__ float    g_xT[F_DIM * B_DIM];        // [f][b] (1.6MB, L2-resident)
__device__ uint32_t g_W[R_DIM * C_DIM * 56];    // [(r*16+c)][56] half2(A,B), d-padded
__device__ float    g_base[R_DIM * C_DIM];      // [r*16+c]

__device__ __forceinline__ uint32_t pack_h2(float lo, float hi) {
    __half2 h = __floats2half2_rn(lo, hi);      // .x(low)=lo, .y(high)=hi
    return *reinterpret_cast<uint32_t*>(&h);
}

// ---------------------------------------------------------------------------
// Kernel 1: transpose x[b][f] -> xT[f][b].
// ---------------------------------------------------------------------------
__global__ void __launch_bounds__(256) transpose_kernel(const float* __restrict__ x) {
    __shared__ float tile[32][33];
    int fx = blockIdx.x * 32 + threadIdx.x;
    #pragma unroll
    for (int k = 0; k < 32; k += 8) {
        int b = blockIdx.y * 32 + threadIdx.y + k;
        if (fx < F_DIM) tile[threadIdx.y + k][threadIdx.x] = x[b * F_DIM + fx];
    }
    __syncthreads();
    int b_out = blockIdx.y * 32 + threadIdx.x;
    #pragma unroll
    for (int k = 0; k < 32; k += 8) {
        int f = blockIdx.x * 32 + threadIdx.y + k;
        if (f < F_DIM) g_xT[f * B_DIM + b_out] = tile[threadIdx.x][threadIdx.y + k];
    }
}

// ---------------------------------------------------------------------------
// Kernel 2: prep — W coefficients (half2(A,B)) + base, once per r.
//   A = -0.5/s^2 (multiplies x^2, even k), B = loc/s^2 (multiplies x, odd k).
// ---------------------------------------------------------------------------
__global__ void __launch_bounds__(256) prep_kernel(const float* __restrict__ loc,
                                                   const float* __restrict__ scale) {
    int r = blockIdx.x;
    int t = threadIdx.x;
    __shared__ float scon[784];          // [c][d]
    for (int i = t; i < 784; i += 256) {
        int c = i / D_DIM;
        int d = i - c * D_DIM;
        float lc = loc[r * 784 + i];
        float sc = scale[r * 784 + i];
        float A = 0.0f, Bv = 0.0f, contrib = 0.0f;
        if (sc > 0.0f) {
            float inv = 1.0f / sc;
            float w = inv * inv;
            A = -0.5f * w;
            Bv = w * lc;
            contrib = -0.5f * w * lc * lc - __logf(sc) - HALF_LOG_2PI;
        }                                 // else: reference zeroes NaN logp
        g_W[(r * 16 + c) * 56 + d] = pack_h2(A, Bv);
        scon[i] = contrib;
    }
    // zero d-padding 49..55
    for (int i = t; i < 16 * 7; i += 256) {
        int c = i / 7, dl = 49 + (i % 7);
        g_W[(r * 16 + c) * 56 + dl] = 0u;
    }
    __syncthreads();
    if (t < 128) {
        int c = t >> 3, l = t & 7;
        float s = 0.0f;
        for (int d = l; d < D_DIM; d += 8) s += scon[c * D_DIM + d];
        s += __shfl_down_sync(0xffffffffu, s, 4, 8);
        s += __shfl_down_sync(0xffffffffu, s, 2, 8);
        s += __shfl_down_sync(0xffffffffu, s, 1, 8);
        if (l == 0) g_base[r * 16 + c] = s;
    }
}

// ---------------------------------------------------------------------------
// Kernel 3: main — HMMA (mma.sync.m16n8k16, fp16 in / fp32 accum).
// Block = (rp = r-pair, 128-b tile), 256 threads = 8 warps, warp owns 16 rows.
//   D[m=128, n=32] = A[m, K] @ W[n, K]^T, block-diagonal in K:
//   n-tiles {0,1} (r0) use xs2 rows [0,56); {2,3} (r1) rows [56,112).
// A fragments: LDS.32 of prepacked half2(x^2, x) — xs2[d][b], stride 136
//   (bank = (8*d_off + lq) % 32, d_off{0..3} x lq{0..7} -> all 32 distinct).
// B fragments: LDS.32 of half2(A,B) — sW[n][d], stride 60
//   (bank = (28*lq + lr) % 32 -> all 32 distinct).
// Per warp: 2 halves x 7 ksteps x (4 A-LDS + 2x(2 B-LDS + 1 HMMA)) = 28 MMA.
// ---------------------------------------------------------------------------
#define XS_OFF   0        // u32[112][136] = 15232
#define W_OFF    15232    // u32[32][60]   = 1920
#define BASE_OFF 17152    // f32[32]
#define MASK_OFF 17184    // s32[98]
#define SMEM_U32 17282
#define SMEM_BYTES (SMEM_U32 * 4)

__global__ void __launch_bounds__(256) main_kernel(const int* __restrict__ mask,
                                                   float* __restrict__ out) {
    int rp  = blockIdx.x;                 // r0 = 2rp, r1 = 2rp+1
    int bq0 = blockIdx.y * 128;
    int tid = threadIdx.x;

    extern __shared__ uint32_t dyn[];
    uint32_t* xs2   = dyn + XS_OFF;       // [112][136] half2(x^2, x)
    uint32_t* sW    = dyn + W_OFF;        // [32][60]  half2(A, B)
    float*    sbase = reinterpret_cast<float*>(dyn + BASE_OFF);
    int*      smask = reinterpret_cast<int*>(dyn + MASK_OFF);

    if (tid < 98) smask[tid] = mask[rp * 98 + tid];
    if (tid >= 128 && tid < 160) sbase[tid - 128] = g_base[rp * 32 + (tid - 128)];
    __syncthreads();

    // ---- fill xs2: gather x from L2-resident xT, pack (x^2, x) ----
    for (int i = tid; i < 112 * 32; i += 256) {
        int row = i >> 5, q = i & 31;           // row = h*56 + d, q = b/4
        int h = (row >= 56) ? 1 : 0;
        int d = row - h * 56;
        uint4 v = make_uint4(0u, 0u, 0u, 0u);
        if (d < D_DIM) {
            const float4 xv = *reinterpret_cast<const float4*>(
                g_xT + (size_t)smask[h * D_DIM + d] * B_DIM + bq0 + q * 4);
            v.x = pack_h2(xv.x * xv.x, xv.x);
            v.y = pack_h2(xv.y * xv.y, xv.y);
            v.z = pack_h2(xv.z * xv.z, xv.z);
            v.w = pack_h2(xv.w * xv.w, xv.w);
        }
        *reinterpret_cast<uint4*>(xs2 + row * 136 + q * 4) = v;
    }
    // ---- load W tile (repack stride 56 -> 60) ----
    {
        const uint32_t* gw = g_W + (size_t)rp * 32 * 56;
        for (int i = tid; i < 32 * 56; i += 256) {
            int n = i / 56, dl = i - n * 56;
            sW[n * 60 + dl] = gw[i];
        }
    }
    __syncthreads();

    // ---- MMA mainloop ----
    int wid  = tid >> 5;
    int lane = tid & 31;
    int lq = lane >> 2;                   // 0..7
    int lr = lane & 3;                    // 0..3
    int m0 = wid * 16;

    float acc[4][4];                      // [ntile][c0..c3]
    #pragma unroll
    for (int t = 0; t < 4; ++t)
        #pragma unroll
        for (int j = 0; j < 4; ++j) acc[t][j] = 0.0f;

    const uint32_t* xA = xs2 + lr * 136 + m0 + lq;   // + (h*56+ks*8[+4])*136 [+8]
    const uint32_t* wB = sW + lq * 60 + lr;          // + t*480 + ks*8 [+4]

    #pragma unroll
    for (int h = 0; h < 2; ++h) {
        #pragma unroll
        for (int ks = 0; ks < 7; ++ks) {
            int xo = (h * 56 + ks * 8) * 136;
            uint32_t a0 = xA[xo];
            uint32_t a1 = xA[xo + 8];
            uint32_t a2 = xA[xo + 4 * 136];
            uint32_t a3 = xA[xo + 4 * 136 + 8];
            #pragma unroll
            for (int tt = 0; tt < 2; ++tt) {
                int t = h * 2 + tt;
                int wo = t * 8 * 60 + ks * 8;
                uint32_t b0 = wB[wo];
                uint32_t b1 = wB[wo + 4];
                asm volatile(
                    "mma.sync.aligned.m16n8k16.row.col.f32.f16.f16.f32 "
                    "{%0,%1,%2,%3}, {%4,%5,%6,%7}, {%8,%9}, {%0,%1,%2,%3};"
                    : "+f"(acc[t][0]), "+f"(acc[t][1]),
                      "+f"(acc[t][2]), "+f"(acc[t][3])
                    : "r"(a0), "r"(a1), "r"(a2), "r"(a3), "r"(b0), "r"(b1));
            }
        }
    }

    // ---- epilogue: add base, store float2 pairs ----
    #pragma unroll
    for (int t = 0; t < 4; ++t) {
        int nc = t * 8 + lr * 2;                    // 0..31
        float bb0 = sbase[nc];
        float bb1 = sbase[nc + 1];
        size_t col = (size_t)rp * 32 + nc;
        size_t row0 = (size_t)(bq0 + m0 + lq) * (R_DIM * C_DIM);
        size_t row1 = row0 + 8 * (R_DIM * C_DIM);
        *reinterpret_cast<float2*>(out + row0 + col)
            = make_float2(acc[t][0] + bb0, acc[t][1] + bb1);
        *reinterpret_cast<float2*>(out + row1 + col)
            = make_float2(acc[t][2] + bb0, acc[t][3] + bb1);
    }
}

// ---------------------------------------------------------------------------
extern "C" void kernel_launch(void* const* d_in, const int* in_sizes, int n_in,
                              void* d_out, int out_size) {
    const float* x     = (const float*)d_in[0];
    const int*   mask  = (const int*)d_in[1];
    const float* loc   = (const float*)d_in[2];
    const float* scale = (const float*)d_in[3];
    float* out = (float*)d_out;

    cudaFuncSetAttribute(main_kernel, cudaFuncAttributeMaxDynamicSharedMemorySize,
                         SMEM_BYTES);
    transpose_kernel<<<dim3((F_DIM + 31) / 32, B_DIM / 32), dim3(32, 8)>>>(x);
    prep_kernel<<<R_DIM, 256>>>(loc, scale);
    main_kernel<<<dim3(R_DIM / 2, B_DIM / 128), 256, SMEM_BYTES>>>(mask, out);
}

// round 14
// speedup vs baseline: 1.4743x; 1.4743x over previous
#include <cuda_runtime.h>
#include <cuda_fp16.h>
#include <cstdint>

#define B_DIM 512
#define F_DIM 784
#define R_DIM 512
#define C_DIM 16
#define D_DIM 49
#define HALF_LOG_2PI 0.9189385332046727f

// Scratch (allocation-free rule: __device__ globals)
__device__ float    g_xT[F_DIM * B_DIM];        // [f][b] (1.6MB, L2-resident)
__device__ uint32_t g_W[R_DIM * C_DIM * 56];    // [(r*16+c)][56] half2(A,B), d-padded
__device__ float    g_base[R_DIM * C_DIM];      // [r*16+c]

__device__ __forceinline__ uint32_t pack_h2(float lo, float hi) {
    __half2 h = __floats2half2_rn(lo, hi);      // .x(low)=lo, .y(high)=hi
    return *reinterpret_cast<uint32_t*>(&h);
}
__device__ __forceinline__ uint32_t smem_u32(const void* p) {
    uint32_t a;
    asm("{ .reg .u64 t; cvta.to.shared.u64 t, %1; cvt.u32.u64 %0, t; }" : "=r"(a) : "l"(p));
    return a;
}
__device__ __forceinline__ void cp_async16(uint32_t dst, const void* src) {
    asm volatile("cp.async.cg.shared.global [%0], [%1], 16;" :: "r"(dst), "l"(src));
}

// ---------------------------------------------------------------------------
// Kernel 1 (merged): blocks 0..399 transpose x -> xT; blocks 400..911 prep
// W coefficients (half2(A,B), A=-0.5/s^2 even k, B=loc/s^2 odd k) + base.
// Both halves are latency-bound -> running them concurrently hides ~4.5us.
// ---------------------------------------------------------------------------
__global__ void __launch_bounds__(256) setup_kernel(const float* __restrict__ x,
                                                    const float* __restrict__ loc,
                                                    const float* __restrict__ scale) {
    __shared__ float tile[32][33];
    __shared__ float scon[784];

    if (blockIdx.x < 400) {
        // ---- transpose ----
        int bx = blockIdx.x % 25;            // f block
        int by = blockIdx.x / 25;            // b block
        int tx = threadIdx.x & 31, ty = threadIdx.x >> 5;
        int fx = bx * 32 + tx;
        #pragma unroll
        for (int k = 0; k < 32; k += 8) {
            int b = by * 32 + ty + k;
            if (fx < F_DIM) tile[ty + k][tx] = x[b * F_DIM + fx];
        }
        __syncthreads();
        int b_out = by * 32 + tx;
        #pragma unroll
        for (int k = 0; k < 32; k += 8) {
            int f = bx * 32 + ty + k;
            if (f < F_DIM) g_xT[f * B_DIM + b_out] = tile[tx][ty + k];
        }
    } else {
        // ---- prep ----
        int r = blockIdx.x - 400;
        int t = threadIdx.x;
        for (int i = t; i < 784; i += 256) {
            int c = i / D_DIM;
            int d = i - c * D_DIM;
            float lc = loc[r * 784 + i];
            float sc = scale[r * 784 + i];
            float A = 0.0f, Bv = 0.0f, contrib = 0.0f;
            if (sc > 0.0f) {
                float inv = 1.0f / sc;
                float w = inv * inv;
                A = -0.5f * w;
                Bv = w * lc;
                contrib = -0.5f * w * lc * lc - __logf(sc) - HALF_LOG_2PI;
            }                                 // else: reference zeroes NaN logp
            g_W[(r * 16 + c) * 56 + d] = pack_h2(A, Bv);
            scon[i] = contrib;
        }
        for (int i = t; i < 16 * 7; i += 256) {
            int c = i / 7, dl = 49 + (i % 7);
            g_W[(r * 16 + c) * 56 + dl] = 0u;
        }
        __syncthreads();
        if (t < 128) {
            int c = t >> 3, l = t & 7;
            float s = 0.0f;
            for (int d = l; d < D_DIM; d += 8) s += scon[c * D_DIM + d];
            s += __shfl_down_sync(0xffffffffu, s, 4, 8);
            s += __shfl_down_sync(0xffffffffu, s, 2, 8);
            s += __shfl_down_sync(0xffffffffu, s, 1, 8);
            if (l == 0) g_base[r * 16 + c] = s;
        }
    }
}

// ---------------------------------------------------------------------------
// Kernel 2: main — HMMA (mma.sync.m16n8k16, fp16 in / fp32 accum), pipelined.
// Block = (rp = r-pair, 128-b tile), 256 threads = 8 warps, warp owns 16 rows.
//   D[m=128, n=32] = A[m,K] @ W[n,K]^T; block-diagonal: ntiles {0,1} (r0)
//   use xs2 rows [0,56), ntiles {2,3} (r1) rows [56,112).
// Pipeline: LDG h0 -> STS h0 -> LDG h1 (in flight) -> sync -> MMA h0
//           -> STS h1 -> sync -> MMA h1.  W tile arrives via cp.async.
// ---------------------------------------------------------------------------
#define XS_OFF   0        // u32[112][136] = 15232
#define W_OFF    15232    // u32[32][60]   = 1920
#define BASE_OFF 17152    // f32[32]
#define MASK_OFF 17184    // s32[98]
#define SMEM_U32 17282
#define SMEM_BYTES (SMEM_U32 * 4)

__global__ void __launch_bounds__(256, 3) main_kernel(const int* __restrict__ mask,
                                                      float* __restrict__ out) {
    int rp  = blockIdx.x;                 // r0 = 2rp, r1 = 2rp+1
    int bq0 = blockIdx.y * 128;
    int tid = threadIdx.x;

    extern __shared__ uint32_t dyn[];
    uint32_t* xs2   = dyn + XS_OFF;       // [112][136] half2(x^2, x)
    uint32_t* sW    = dyn + W_OFF;        // [32][60]  half2(A, B)
    float*    sbase = reinterpret_cast<float*>(dyn + BASE_OFF);
    int*      smask = reinterpret_cast<int*>(dyn + MASK_OFF);

    // ---- W tile via cp.async (56 -> 60 u32 stride; 16B chunks, both aligned) ----
    {
        const uint32_t* gw = g_W + (size_t)rp * 32 * 56;
        uint32_t wbase = smem_u32(sW);
        for (int i = tid; i < 32 * 14; i += 256) {     // 448 16B chunks
            int n = i / 14, ch = i - n * 14;
            cp_async16(wbase + (uint32_t)(n * 60 + ch * 4) * 4u, gw + n * 56 + ch * 4);
        }
        asm volatile("cp.async.commit_group;");
    }
    if (tid < 98) smask[tid] = mask[rp * 98 + tid];
    if (tid >= 128 && tid < 160) sbase[tid - 128] = g_base[rp * 32 + (tid - 128)];
    __syncthreads();

    // ---- gather: 14 rows/thread (7 in h0, 7 in h1), q = b/4 ----
    int rbase = tid >> 5;                  // 0..7
    int q     = tid & 31;
    uint4 v[7];

    // h0 loads (rows 0..55)
    #pragma unroll
    for (int k = 0; k < 7; ++k) {
        int d = rbase + 8 * k;
        v[k] = make_uint4(0u, 0u, 0u, 0u);
        if (d < D_DIM) {
            float4 xv = *reinterpret_cast<const float4*>(
                g_xT + (size_t)smask[d] * B_DIM + bq0 + q * 4);
            v[k].x = pack_h2(xv.x * xv.x, xv.x);
            v[k].y = pack_h2(xv.y * xv.y, xv.y);
            v[k].z = pack_h2(xv.z * xv.z, xv.z);
            v[k].w = pack_h2(xv.w * xv.w, xv.w);
        }
    }
    #pragma unroll
    for (int k = 0; k < 7; ++k)
        *reinterpret_cast<uint4*>(xs2 + (rbase + 8 * k) * 136 + q * 4) = v[k];

    // h1 loads issued now — in flight during sync + MMA h0
    #pragma unroll
    for (int k = 0; k < 7; ++k) {
        int d = rbase + 8 * k;
        v[k] = make_uint4(0u, 0u, 0u, 0u);
        if (d < D_DIM) {
            float4 xv = *reinterpret_cast<const float4*>(
                g_xT + (size_t)smask[D_DIM + d] * B_DIM + bq0 + q * 4);
            v[k].x = pack_h2(xv.x * xv.x, xv.x);
            v[k].y = pack_h2(xv.y * xv.y, xv.y);
            v[k].z = pack_h2(xv.z * xv.z, xv.z);
            v[k].w = pack_h2(xv.w * xv.w, xv.w);
        }
    }

    asm volatile("cp.async.wait_group 0;");       // W resident
    __syncthreads();                              // xs2 h0 + sW visible

    // ---- MMA setup ----
    int wid  = tid >> 5;
    int lane = tid & 31;
    int lq = lane >> 2;                   // 0..7
    int lr = lane & 3;                    // 0..3
    int m0 = wid * 16;

    float acc[4][4];                      // [ntile][c0..c3]
    #pragma unroll
    for (int t = 0; t < 4; ++t)
        #pragma unroll
        for (int j = 0; j < 4; ++j) acc[t][j] = 0.0f;

    const uint32_t* xA = xs2 + lr * 136 + m0 + lq;
    const uint32_t* wB = sW + lq * 60 + lr;

    // ---- MMA h0 (ntiles 0,1 <- xs2 rows [0,56)) ----
    #pragma unroll
    for (int ks = 0; ks < 7; ++ks) {
        int xo = (ks * 8) * 136;
        uint32_t a0 = xA[xo];
        uint32_t a1 = xA[xo + 8];
        uint32_t a2 = xA[xo + 4 * 136];
        uint32_t a3 = xA[xo + 4 * 136 + 8];
        #pragma unroll
        for (int t = 0; t < 2; ++t) {
            int wo = t * 8 * 60 + ks * 8;
            uint32_t b0 = wB[wo];
            uint32_t b1 = wB[wo + 4];
            asm volatile(
                "mma.sync.aligned.m16n8k16.row.col.f32.f16.f16.f32 "
                "{%0,%1,%2,%3}, {%4,%5,%6,%7}, {%8,%9}, {%0,%1,%2,%3};"
                : "+f"(acc[t][0]), "+f"(acc[t][1]), "+f"(acc[t][2]), "+f"(acc[t][3])
                : "r"(a0), "r"(a1), "r"(a2), "r"(a3), "r"(b0), "r"(b1));
        }
    }
    __syncthreads();                              // all warps done reading... (h0 rows stay)

    // ---- store h1, sync, MMA h1 ----
    #pragma unroll
    for (int k = 0; k < 7; ++k)
        *reinterpret_cast<uint4*>(xs2 + (56 + rbase + 8 * k) * 136 + q * 4) = v[k];
    __syncthreads();

    #pragma unroll
    for (int ks = 0; ks < 7; ++ks) {
        int xo = (56 + ks * 8) * 136;
        uint32_t a0 = xA[xo];
        uint32_t a1 = xA[xo + 8];
        uint32_t a2 = xA[xo + 4 * 136];
        uint32_t a3 = xA[xo + 4 * 136 + 8];
        #pragma unroll
        for (int tt = 0; tt < 2; ++tt) {
            int t = 2 + tt;
            int wo = t * 8 * 60 + ks * 8;
            uint32_t b0 = wB[wo];
            uint32_t b1 = wB[wo + 4];
            asm volatile(
                "mma.sync.aligned.m16n8k16.row.col.f32.f16.f16.f32 "
                "{%0,%1,%2,%3}, {%4,%5,%6,%7}, {%8,%9}, {%0,%1,%2,%3};"
                : "+f"(acc[t][0]), "+f"(acc[t][1]), "+f"(acc[t][2]), "+f"(acc[t][3])
                : "r"(a0), "r"(a1), "r"(a2), "r"(a3), "r"(b0), "r"(b1));
        }
    }

    // ---- epilogue: add base, store float2 pairs ----
    #pragma unroll
    for (int t = 0; t < 4; ++t) {
        int nc = t * 8 + lr * 2;                    // 0..31
        float bb0 = sbase[nc];
        float bb1 = sbase[nc + 1];
        size_t col = (size_t)rp * 32 + nc;
        size_t row0 = (size_t)(bq0 + m0 + lq) * (R_DIM * C_DIM);
        size_t row1 = row0 + 8 * (R_DIM * C_DIM);
        *reinterpret_cast<float2*>(out + row0 + col)
            = make_float2(acc[t][0] + bb0, acc[t][1] + bb1);
        *reinterpret_cast<float2*>(out + row1 + col)
            = make_float2(acc[t][2] + bb0, acc[t][3] + bb1);
    }
}

// ---------------------------------------------------------------------------
extern "C" void kernel_launch(void* const* d_in, const int* in_sizes, int n_in,
                              void* d_out, int out_size) {
    const float* x     = (const float*)d_in[0];
    const int*   mask  = (const int*)d_in[1];
    const float* loc   = (const float*)d_in[2];
    const float* scale = (const float*)d_in[3];
    float* out = (float*)d_out;

    cudaFuncSetAttribute(main_kernel, cudaFuncAttributeMaxDynamicSharedMemorySize,
                         SMEM_BYTES);
    setup_kernel<<<912, 256>>>(x, loc, scale);
    main_kernel<<<dim3(R_DIM / 2, B_DIM / 128), 256, SMEM_BYTES>>>(mask, out);
}

// round 15
// speedup vs baseline: 1.6294x; 1.1052x over previous
#include <cuda_runtime.h>
#include <cuda_fp16.h>
#include <cstdint>

#define B_DIM 512
#define F_DIM 784
#define R_DIM 512
#define C_DIM 16
#define D_DIM 49
#define HALF_LOG_2PI 0.9189385332046727f

// Scratch (allocation-free rule: __device__ globals)
__device__ uint32_t g_x2T[F_DIM * B_DIM];       // [f][b] half2(x^2, x) (1.6MB, L2)
__device__ uint32_t g_W[R_DIM * C_DIM * 56];    // [(r*16+c)][56] half2(A,B), d-padded
__device__ float    g_base[R_DIM * C_DIM];      // [r*16+c]

__device__ __forceinline__ uint32_t pack_h2(float lo, float hi) {
    __half2 h = __floats2half2_rn(lo, hi);      // .x(low)=lo, .y(high)=hi
    return *reinterpret_cast<uint32_t*>(&h);
}
__device__ __forceinline__ uint32_t smem_u32(const void* p) {
    uint32_t a;
    asm("{ .reg .u64 t; cvta.to.shared.u64 t, %1; cvt.u32.u64 %0, t; }" : "=r"(a) : "l"(p));
    return a;
}
__device__ __forceinline__ void cp_async16(uint32_t dst, const void* src) {
    asm volatile("cp.async.cg.shared.global [%0], [%1], 16;" :: "r"(dst), "l"(src));
}

// ---------------------------------------------------------------------------
// Kernel 1 (merged): blocks 0..399 transpose+pack x -> x2T = half2(x^2, x);
// blocks 400..911 prep W coefficients (half2(A,B)) + base.
// Both halves latency-bound -> concurrent execution hides ~4.5us.
// ---------------------------------------------------------------------------
__global__ void __launch_bounds__(256) setup_kernel(const float* __restrict__ x,
                                                    const float* __restrict__ loc,
                                                    const float* __restrict__ scale) {
    __shared__ float tile[32][33];
    __shared__ float scon[784];

    if (blockIdx.x < 400) {
        // ---- transpose + pack ----
        int bx = blockIdx.x % 25;            // f block
        int by = blockIdx.x / 25;            // b block
        int tx = threadIdx.x & 31, ty = threadIdx.x >> 5;
        int fx = bx * 32 + tx;
        #pragma unroll
        for (int k = 0; k < 32; k += 8) {
            int b = by * 32 + ty + k;
            if (fx < F_DIM) tile[ty + k][tx] = x[b * F_DIM + fx];
        }
        __syncthreads();
        int b_out = by * 32 + tx;
        #pragma unroll
        for (int k = 0; k < 32; k += 8) {
            int f = bx * 32 + ty + k;
            if (f < F_DIM) {
                float v = tile[tx][ty + k];
                g_x2T[f * B_DIM + b_out] = pack_h2(v * v, v);
            }
        }
    } else {
        // ---- prep ----
        int r = blockIdx.x - 400;
        int t = threadIdx.x;
        for (int i = t; i < 784; i += 256) {
            int c = i / D_DIM;
            int d = i - c * D_DIM;
            float lc = loc[r * 784 + i];
            float sc = scale[r * 784 + i];
            float A = 0.0f, Bv = 0.0f, contrib = 0.0f;
            if (sc > 0.0f) {
                float inv = 1.0f / sc;
                float w = inv * inv;
                A = -0.5f * w;
                Bv = w * lc;
                contrib = -0.5f * w * lc * lc - __logf(sc) - HALF_LOG_2PI;
            }                                 // else: reference zeroes NaN logp
            g_W[(r * 16 + c) * 56 + d] = pack_h2(A, Bv);
            scon[i] = contrib;
        }
        for (int i = t; i < 16 * 7; i += 256) {
            int c = i / 7, dl = 49 + (i % 7);
            g_W[(r * 16 + c) * 56 + dl] = 0u;
        }
        __syncthreads();
        if (t < 128) {
            int c = t >> 3, l = t & 7;
            float s = 0.0f;
            for (int d = l; d < D_DIM; d += 8) s += scon[c * D_DIM + d];
            s += __shfl_down_sync(0xffffffffu, s, 4, 8);
            s += __shfl_down_sync(0xffffffffu, s, 2, 8);
            s += __shfl_down_sync(0xffffffffu, s, 1, 8);
            if (l == 0) g_base[r * 16 + c] = s;
        }
    }
}

// ---------------------------------------------------------------------------
// Kernel 2: main — HMMA (mma.sync.m16n8k16, fp16 in / fp32 accum).
// Block = (rp = r-pair, 128-b tile), 256 threads = 8 warps, warp owns 16 rows.
//   D[m=128, n=32] = A[m,K] @ W[n,K]^T; block-diagonal: ntiles {0,1} (r0)
//   use xs2 rows [0,56), ntiles {2,3} (r1) rows [56,112).
// ALL operand movement is cp.async from pre-packed tables — no convert math,
// no STS staging. Commit groups: W | h0 | h1; MMA h0 runs while h1 lands.
// ---------------------------------------------------------------------------
#define XS_OFF   0        // u32[112][136] = 15232
#define W_OFF    15232    // u32[32][60]   = 1920
#define BASE_OFF 17152    // f32[32]
#define MASK_OFF 17184    // s32[98]
#define SMEM_U32 17282
#define SMEM_BYTES (SMEM_U32 * 4)

__global__ void __launch_bounds__(256, 3) main_kernel(const int* __restrict__ mask,
                                                      float* __restrict__ out) {
    int rp  = blockIdx.x;                 // r0 = 2rp, r1 = 2rp+1
    int bq0 = blockIdx.y * 128;
    int tid = threadIdx.x;

    extern __shared__ uint32_t dyn[];
    uint32_t* xs2   = dyn + XS_OFF;       // [112][136] half2(x^2, x)
    uint32_t* sW    = dyn + W_OFF;        // [32][60]  half2(A, B)
    float*    sbase = reinterpret_cast<float*>(dyn + BASE_OFF);
    int*      smask = reinterpret_cast<int*>(dyn + MASK_OFF);
    uint32_t xs_b = smem_u32(xs2);

    // ---- group 0: W tile (56 -> 60 u32 stride; 16B chunks, both aligned) ----
    {
        const uint32_t* gw = g_W + (size_t)rp * 32 * 56;
        uint32_t wbase = smem_u32(sW);
        for (int i = tid; i < 32 * 14; i += 256) {     // 448 16B chunks
            int n = i / 14, ch = i - n * 14;
            cp_async16(wbase + (uint32_t)(n * 60 + ch * 4) * 4u, gw + n * 56 + ch * 4);
        }
        asm volatile("cp.async.commit_group;");
    }
    if (tid < 98) smask[tid] = mask[rp * 98 + tid];
    if (tid >= 128 && tid < 160) sbase[tid - 128] = g_base[rp * 32 + (tid - 128)];
    // zero pad rows d = 49..55 of both halves (rows 49-55, 105-111)
    for (int i = tid; i < 448; i += 256) {
        int rr = i >> 5, q = i & 31;
        int row = (rr < 7) ? (49 + rr) : (98 + rr);
        *reinterpret_cast<uint4*>(xs2 + row * 136 + q * 4) = make_uint4(0u, 0u, 0u, 0u);
    }
    __syncthreads();                      // smask visible; pad rows safe (disjoint)

    // ---- group 1: h0 rows (d = 0..48), group 2: h1 rows ----
    for (int i = tid; i < 49 * 32; i += 256) {
        int d = i >> 5, q = i & 31;
        cp_async16(xs_b + (uint32_t)(d * 136 + q * 4) * 4u,
                   g_x2T + (size_t)smask[d] * B_DIM + bq0 + q * 4);
    }
    asm volatile("cp.async.commit_group;");
    for (int i = tid; i < 49 * 32; i += 256) {
        int d = i >> 5, q = i & 31;
        cp_async16(xs_b + (uint32_t)((56 + d) * 136 + q * 4) * 4u,
                   g_x2T + (size_t)smask[D_DIM + d] * B_DIM + bq0 + q * 4);
    }
    asm volatile("cp.async.commit_group;");

    // ---- MMA setup ----
    int wid  = tid >> 5;
    int lane = tid & 31;
    int lq = lane >> 2;                   // 0..7
    int lr = lane & 3;                    // 0..3
    int m0 = wid * 16;

    float acc[4][4];                      // [ntile][c0..c3]
    #pragma unroll
    for (int t = 0; t < 4; ++t)
        #pragma unroll
        for (int j = 0; j < 4; ++j) acc[t][j] = 0.0f;

    const uint32_t* xA = xs2 + lr * 136 + m0 + lq;
    const uint32_t* wB = sW + lq * 60 + lr;

    asm volatile("cp.async.wait_group 1;");       // W + h0 resident
    __syncthreads();

    // ---- MMA h0 (ntiles 0,1 <- xs2 rows [0,56)) ----
    #pragma unroll
    for (int ks = 0; ks < 7; ++ks) {
        int xo = (ks * 8) * 136;
        uint32_t a0 = xA[xo];
        uint32_t a1 = xA[xo + 8];
        uint32_t a2 = xA[xo + 4 * 136];
        uint32_t a3 = xA[xo + 4 * 136 + 8];
        #pragma unroll
        for (int t = 0; t < 2; ++t) {
            int wo = t * 8 * 60 + ks * 8;
            uint32_t b0 = wB[wo];
            uint32_t b1 = wB[wo + 4];
            asm volatile(
                "mma.sync.aligned.m16n8k16.row.col.f32.f16.f16.f32 "
                "{%0,%1,%2,%3}, {%4,%5,%6,%7}, {%8,%9}, {%0,%1,%2,%3};"
                : "+f"(acc[t][0]), "+f"(acc[t][1]), "+f"(acc[t][2]), "+f"(acc[t][3])
                : "r"(a0), "r"(a1), "r"(a2), "r"(a3), "r"(b0), "r"(b1));
        }
    }

    asm volatile("cp.async.wait_group 0;");       // h1 resident
    __syncthreads();

    // ---- MMA h1 (ntiles 2,3 <- xs2 rows [56,112)) ----
    #pragma unroll
    for (int ks = 0; ks < 7; ++ks) {
        int xo = (56 + ks * 8) * 136;
        uint32_t a0 = xA[xo];
        uint32_t a1 = xA[xo + 8];
        uint32_t a2 = xA[xo + 4 * 136];
        uint32_t a3 = xA[xo + 4 * 136 + 8];
        #pragma unroll
        for (int tt = 0; tt < 2; ++tt) {
            int t = 2 + tt;
            int wo = t * 8 * 60 + ks * 8;
            uint32_t b0 = wB[wo];
            uint32_t b1 = wB[wo + 4];
            asm volatile(
                "mma.sync.aligned.m16n8k16.row.col.f32.f16.f16.f32 "
                "{%0,%1,%2,%3}, {%4,%5,%6,%7}, {%8,%9}, {%0,%1,%2,%3};"
                : "+f"(acc[t][0]), "+f"(acc[t][1]), "+f"(acc[t][2]), "+f"(acc[t][3])
                : "r"(a0), "r"(a1), "r"(a2), "r"(a3), "r"(b0), "r"(b1));
        }
    }

    // ---- epilogue: add base, store float2 pairs ----
    #pragma unroll
    for (int t = 0; t < 4; ++t) {
        int nc = t * 8 + lr * 2;                    // 0..31
        float bb0 = sbase[nc];
        float bb1 = sbase[nc + 1];
        size_t col = (size_t)rp * 32 + nc;
        size_t row0 = (size_t)(bq0 + m0 + lq) * (R_DIM * C_DIM);
        size_t row1 = row0 + 8 * (R_DIM * C_DIM);
        *reinterpret_cast<float2*>(out + row0 + col)
            = make_float2(acc[t][0] + bb0, acc[t][1] + bb1);
        *reinterpret_cast<float2*>(out + row1 + col)
            = make_float2(acc[t][2] + bb0, acc[t][3] + bb1);
    }
}

// ---------------------------------------------------------------------------
extern "C" void kernel_launch(void* const* d_in, const int* in_sizes, int n_in,
                              void* d_out, int out_size) {
    const float* x     = (const float*)d_in[0];
    const int*   mask  = (const int*)d_in[1];
    const float* loc   = (const float*)d_in[2];
    const float* scale = (const float*)d_in[3];
    float* out = (float*)d_out;

    cudaFuncSetAttribute(main_kernel, cudaFuncAttributeMaxDynamicSharedMemorySize,
                         SMEM_BYTES);
    setup_kernel<<<912, 256>>>(x, loc, scale);
    main_kernel<<<dim3(R_DIM / 2, B_DIM / 128), 256, SMEM_BYTES>>>(mask, out);
}

// round 16
// speedup vs baseline: 1.6542x; 1.0153x over previous
#include <cuda_runtime.h>
#include <cuda_fp16.h>
#include <cstdint>

#define B_DIM 512
#define F_DIM 784
#define R_DIM 512
#define C_DIM 16
#define D_DIM 49
#define HALF_LOG_2PI 0.9189385332046727f

// Scratch (allocation-free rule: __device__ globals)
__device__ uint32_t g_x2T[F_DIM * B_DIM];       // [f][b] half2(x^2, x) (1.6MB, L2)
__device__ uint32_t g_W[R_DIM * C_DIM * 56];    // [(r*16+c)][56] half2(A,B), d-padded
__device__ float    g_base[R_DIM * C_DIM];      // [r*16+c]

__device__ __forceinline__ uint32_t pack_h2(float lo, float hi) {
    __half2 h = __floats2half2_rn(lo, hi);      // .x(low)=lo, .y(high)=hi
    return *reinterpret_cast<uint32_t*>(&h);
}
__device__ __forceinline__ uint32_t smem_u32(const void* p) {
    uint32_t a;
    asm("{ .reg .u64 t; cvta.to.shared.u64 t, %1; cvt.u32.u64 %0, t; }" : "=r"(a) : "l"(p));
    return a;
}
__device__ __forceinline__ void cp_async16(uint32_t dst, const void* src) {
    asm volatile("cp.async.cg.shared.global [%0], [%1], 16;" :: "r"(dst), "l"(src));
}

// ---------------------------------------------------------------------------
// Kernel 1 (merged): blocks 0..399 transpose+pack x -> x2T = half2(x^2, x);
// blocks 400..911 prep W coefficients (half2(A,B)) + base.
// ---------------------------------------------------------------------------
__global__ void __launch_bounds__(256) setup_kernel(const float* __restrict__ x,
                                                    const float* __restrict__ loc,
                                                    const float* __restrict__ scale) {
    __shared__ float tile[32][33];
    __shared__ float scon[784];

    if (blockIdx.x < 400) {
        // ---- transpose + pack ----
        int bx = blockIdx.x % 25;            // f block
        int by = blockIdx.x / 25;            // b block
        int tx = threadIdx.x & 31, ty = threadIdx.x >> 5;
        int fx = bx * 32 + tx;
        #pragma unroll
        for (int k = 0; k < 32; k += 8) {
            int b = by * 32 + ty + k;
            if (fx < F_DIM) tile[ty + k][tx] = x[b * F_DIM + fx];
        }
        __syncthreads();
        int b_out = by * 32 + tx;
        #pragma unroll
        for (int k = 0; k < 32; k += 8) {
            int f = bx * 32 + ty + k;
            if (f < F_DIM) {
                float v = tile[tx][ty + k];
                g_x2T[f * B_DIM + b_out] = pack_h2(v * v, v);
            }
        }
    } else {
        // ---- prep ----
        int r = blockIdx.x - 400;
        int t = threadIdx.x;
        for (int i = t; i < 784; i += 256) {
            int c = i / D_DIM;
            int d = i - c * D_DIM;
            float lc = loc[r * 784 + i];
            float sc = scale[r * 784 + i];
            float A = 0.0f, Bv = 0.0f, contrib = 0.0f;
            if (sc > 0.0f) {
                float inv = 1.0f / sc;
                float w = inv * inv;
                A = -0.5f * w;
                Bv = w * lc;
                contrib = -0.5f * w * lc * lc - __logf(sc) - HALF_LOG_2PI;
            }                                 // else: reference zeroes NaN logp
            g_W[(r * 16 + c) * 56 + d] = pack_h2(A, Bv);
            scon[i] = contrib;
        }
        for (int i = t; i < 16 * 7; i += 256) {
            int c = i / 7, dl = 49 + (i % 7);
            g_W[(r * 16 + c) * 56 + dl] = 0u;
        }
        __syncthreads();
        if (t < 128) {
            int c = t >> 3, l = t & 7;
            float s = 0.0f;
            for (int d = l; d < D_DIM; d += 8) s += scon[c * D_DIM + d];
            s += __shfl_down_sync(0xffffffffu, s, 4, 8);
            s += __shfl_down_sync(0xffffffffu, s, 2, 8);
            s += __shfl_down_sync(0xffffffffu, s, 1, 8);
            if (l == 0) g_base[r * 16 + c] = s;
        }
    }
}

// ---------------------------------------------------------------------------
// Kernel 2: main — HMMA (mma.sync.m16n8k16, fp16 in / fp32 accum).
// Block = (ONE r, 128-b tile), 256 threads = 8 warps, warp owns 16 m-rows.
//   D[m=128, n=16] = A[m, K=112] @ W[n, K]^T.
// smem ~34.6KB -> 6 blocks/SM (vs 3 with r-pairs): doubles latency hiding.
// Commit groups: W | rows 0..31 (ks 0..3) | rows 32..55 (ks 4..6);
// MMA phase A runs while group B lands.
// ---------------------------------------------------------------------------
#define XS_OFF   0        // u32[56][136] = 7616
#define W_OFF    7616     // u32[16][60]  = 960
#define BASE_OFF 8576     // f32[16]
#define MASK_OFF 8592     // s32[49]
#define SMEM_U32 8644
#define SMEM_BYTES (SMEM_U32 * 4)

__global__ void __launch_bounds__(256, 6) main_kernel(const int* __restrict__ mask,
                                                      float* __restrict__ out) {
    int r   = blockIdx.x;
    int bq0 = blockIdx.y * 128;
    int tid = threadIdx.x;

    extern __shared__ uint32_t dyn[];
    uint32_t* xs2   = dyn + XS_OFF;       // [56][136] half2(x^2, x)
    uint32_t* sW    = dyn + W_OFF;        // [16][60]  half2(A, B)
    float*    sbase = reinterpret_cast<float*>(dyn + BASE_OFF);
    int*      smask = reinterpret_cast<int*>(dyn + MASK_OFF);
    uint32_t xs_b = smem_u32(xs2);

    // ---- group 0: W tile (56 -> 60 u32 stride; 16B chunks, both aligned) ----
    {
        const uint32_t* gw = g_W + (size_t)r * 16 * 56;
        uint32_t wbase = smem_u32(sW);
        for (int i = tid; i < 16 * 14; i += 256) {     // 224 16B chunks
            int n = i / 14, ch = i - n * 14;
            cp_async16(wbase + (uint32_t)(n * 60 + ch * 4) * 4u, gw + n * 56 + ch * 4);
        }
        asm volatile("cp.async.commit_group;");
    }
    if (tid < 49) smask[tid] = mask[r * 49 + tid];
    if (tid >= 64 && tid < 80) sbase[tid - 64] = g_base[r * 16 + (tid - 64)];
    // zero pad rows d = 49..55
    for (int i = tid; i < 224; i += 256) {
        int rr = i >> 5, q = i & 31;
        *reinterpret_cast<uint4*>(xs2 + (49 + rr) * 136 + q * 4)
            = make_uint4(0u, 0u, 0u, 0u);
    }
    __syncthreads();                      // smask visible

    // ---- group 1: rows 0..31 (ksteps 0..3) ----
    #pragma unroll
    for (int i = tid; i < 32 * 32; i += 256) {
        int d = i >> 5, q = i & 31;
        cp_async16(xs_b + (uint32_t)(d * 136 + q * 4) * 4u,
                   g_x2T + (size_t)smask[d] * B_DIM + bq0 + q * 4);
    }
    asm volatile("cp.async.commit_group;");
    // ---- group 2: rows 32..48 (ksteps 4..6) ----
    for (int i = tid; i < 17 * 32; i += 256) {
        int d = 32 + (i >> 5), q = i & 31;
        cp_async16(xs_b + (uint32_t)(d * 136 + q * 4) * 4u,
                   g_x2T + (size_t)smask[d] * B_DIM + bq0 + q * 4);
    }
    asm volatile("cp.async.commit_group;");

    // ---- MMA setup ----
    int wid  = tid >> 5;
    int lane = tid & 31;
    int lq = lane >> 2;                   // 0..7
    int lr = lane & 3;                    // 0..3
    int m0 = wid * 16;

    float acc[2][4];                      // [ntile][c0..c3]
    #pragma unroll
    for (int t = 0; t < 2; ++t)
        #pragma unroll
        for (int j = 0; j < 4; ++j) acc[t][j] = 0.0f;

    const uint32_t* xA = xs2 + lr * 136 + m0 + lq;
    const uint32_t* wB = sW + lq * 60 + lr;

    asm volatile("cp.async.wait_group 1;");       // W + group A resident
    __syncthreads();

    // ---- MMA phase A (ksteps 0..3, rows 0..31) ----
    #pragma unroll
    for (int ks = 0; ks < 4; ++ks) {
        int xo = (ks * 8) * 136;
        uint32_t a0 = xA[xo];
        uint32_t a1 = xA[xo + 8];
        uint32_t a2 = xA[xo + 4 * 136];
        uint32_t a3 = xA[xo + 4 * 136 + 8];
        #pragma unroll
        for (int t = 0; t < 2; ++t) {
            int wo = t * 8 * 60 + ks * 8;
            uint32_t b0 = wB[wo];
            uint32_t b1 = wB[wo + 4];
            asm volatile(
                "mma.sync.aligned.m16n8k16.row.col.f32.f16.f16.f32 "
                "{%0,%1,%2,%3}, {%4,%5,%6,%7}, {%8,%9}, {%0,%1,%2,%3};"
                : "+f"(acc[t][0]), "+f"(acc[t][1]), "+f"(acc[t][2]), "+f"(acc[t][3])
                : "r"(a0), "r"(a1), "r"(a2), "r"(a3), "r"(b0), "r"(b1));
        }
    }

    asm volatile("cp.async.wait_group 0;");       // group B resident
    __syncthreads();

    // ---- MMA phase B (ksteps 4..6, rows 32..55) ----
    #pragma unroll
    for (int ks = 4; ks < 7; ++ks) {
        int xo = (ks * 8) * 136;
        uint32_t a0 = xA[xo];
        uint32_t a1 = xA[xo + 8];
        uint32_t a2 = xA[xo + 4 * 136];
        uint32_t a3 = xA[xo + 4 * 136 + 8];
        #pragma unroll
        for (int t = 0; t < 2; ++t) {
            int wo = t * 8 * 60 + ks * 8;
            uint32_t b0 = wB[wo];
            uint32_t b1 = wB[wo + 4];
            asm volatile(
                "mma.sync.aligned.m16n8k16.row.col.f32.f16.f16.f32 "
                "{%0,%1,%2,%3}, {%4,%5,%6,%7}, {%8,%9}, {%0,%1,%2,%3};"
                : "+f"(acc[t][0]), "+f"(acc[t][1]), "+f"(acc[t][2]), "+f"(acc[t][3])
                : "r"(a0), "r"(a1), "r"(a2), "r"(a3), "r"(b0), "r"(b1));
        }
    }

    // ---- epilogue: add base, store float2 pairs ----
    #pragma unroll
    for (int t = 0; t < 2; ++t) {
        int nc = t * 8 + lr * 2;                    // 0..15
        float bb0 = sbase[nc];
        float bb1 = sbase[nc + 1];
        size_t col = (size_t)r * 16 + nc;
        size_t row0 = (size_t)(bq0 + m0 + lq) * (R_DIM * C_DIM);
        size_t row1 = row0 + 8 * (R_DIM * C_DIM);
        *reinterpret_cast<float2*>(out + row0 + col)
            = make_float2(acc[t][0] + bb0, acc[t][1] + bb1);
        *reinterpret_cast<float2*>(out + row1 + col)
            = make_float2(acc[t][2] + bb0, acc[t][3] + bb1);
    }
}

// ---------------------------------------------------------------------------
extern "C" void kernel_launch(void* const* d_in, const int* in_sizes, int n_in,
                              void* d_out, int out_size) {
    const float* x     = (const float*)d_in[0];
    const int*   mask  = (const int*)d_in[1];
    const float* loc   = (const float*)d_in[2];
    const float* scale = (const float*)d_in[3];
    float* out = (float*)d_out;

    cudaFuncSetAttribute(main_kernel, cudaFuncAttributeMaxDynamicSharedMemorySize,
                         SMEM_BYTES);
    setup_kernel<<<912, 256>>>(x, loc, scale);
    main_kernel<<<dim3(R_DIM, B_DIM / 128), 256, SMEM_BYTES>>>(mask, out);
}